// round 14
// baseline (speedup 1.0000x reference)
#include <cuda_runtime.h>
#include <cuda_fp16.h>
#include <math.h>
#include <stdint.h>

// Problem constants
#define BB   32
#define LL   512
#define HH   1024
#define QQ   128
#define BQ   (BB * QQ)        // 4096 pair rows
#define K1   (3 * HH)          // 3072
#define N1   256               // VA_H
#define N2   128               // VA_H/2

#define GRID_CTAS 256
#define PREP_BLKS ((N1 * K1 + 255) / 256)   // 3072
#define POOL_JOBS (BQ + PREP_BLKS)          // 7168

// Scratch (static device globals)
__device__ __half g_A[(size_t)BQ * K1];     // pooled pair features, fp16
__device__ __half g_W1[(size_t)N1 * K1];    // fp16 weights
__device__ __half g_W2[(size_t)N2 * N1];
__device__ __half g_x1[(size_t)BQ * N1];    // gelu(layer1), fp16
__device__ unsigned long long g_bar = 0;    // monotonic grid barrier counter

// ---------------------------------------------------------------------------
// helpers
// ---------------------------------------------------------------------------
__device__ __forceinline__ uint32_t smem_u32(const void* p) {
    uint32_t a;
    asm("{ .reg .u64 t; cvta.to.shared.u64 t, %1; cvt.u32.u64 %0, t; }"
        : "=r"(a) : "l"(p));
    return a;
}

#define CP_ASYNC16(dst, src) \
    asm volatile("cp.async.cg.shared.global [%0], [%1], 16;" :: "r"(dst), "l"(src) : "memory")
#define CP_COMMIT() asm volatile("cp.async.commit_group;" ::: "memory")
#define CP_WAIT0()  asm volatile("cp.async.wait_group 0;" ::: "memory")
#define CP_WAIT1()  asm volatile("cp.async.wait_group 1;" ::: "memory")

__device__ __forceinline__ void mma16816(float c[4],
                                         const uint32_t a[4],
                                         const uint32_t b[2])
{
    asm volatile(
        "mma.sync.aligned.m16n8k16.row.col.f32.f16.f16.f32 "
        "{%0,%1,%2,%3}, {%4,%5,%6,%7}, {%8,%9}, {%0,%1,%2,%3};\n"
        : "+f"(c[0]), "+f"(c[1]), "+f"(c[2]), "+f"(c[3])
        : "r"(a[0]), "r"(a[1]), "r"(a[2]), "r"(a[3]),
          "r"(b[0]), "r"(b[1]));
}

__device__ __forceinline__ void ldsm4(uint32_t r[4], uint32_t addr)
{
    asm volatile("ldmatrix.sync.aligned.m8n8.x4.shared.b16 {%0,%1,%2,%3}, [%4];"
        : "=r"(r[0]), "=r"(r[1]), "=r"(r[2]), "=r"(r[3]) : "r"(addr));
}

__device__ __forceinline__ float gelu_exact(float x) {
    return 0.5f * x * (1.0f + erff(x * 0.70710678118654752f));
}

__device__ __forceinline__ void store_h4(__half* dst, size_t idx, float4 v)
{
    __half2 hh[2] = {
        __halves2half2(__float2half_rn(v.x), __float2half_rn(v.y)),
        __halves2half2(__float2half_rn(v.z), __float2half_rn(v.w)) };
    *(uint2*)(dst + idx) = *(uint2*)hh;
}

// ---------------------------------------------------------------------------
// Grid barrier: monotonic counter, replay-safe (never resets), deterministic.
// All gridDim.x blocks must call it the same number of times.
// ---------------------------------------------------------------------------
__device__ __forceinline__ void grid_barrier()
{
    __syncthreads();
    if (threadIdx.x == 0) {
        __threadfence();                                  // release prior writes
        const unsigned long long grid = gridDim.x;
        const unsigned long long old  = atomicAdd(&g_bar, 1ULL);
        const unsigned long long tgt  = (old / grid + 1ULL) * grid;
        unsigned long long v;
        do {
            asm volatile("ld.volatile.global.u64 %0, [%1];" : "=l"(v) : "l"(&g_bar));
        } while (v < tgt);
        __threadfence();                                  // acquire
    }
    __syncthreads();
}

// ---------------------------------------------------------------------------
// Phase 1 body: pooling job (R12 structure, regs-light) or weight prep.
// ---------------------------------------------------------------------------
__device__ __forceinline__ void pool_prep_job(int job,
                                              const float* __restrict__ hs,
                                              const int* __restrict__ spans,
                                              const float* __restrict__ W1,
                                              const float* __restrict__ W2)
{
    const int tid = threadIdx.x;

    if (job >= BQ) {
        const int i = (job - BQ) * 256 + tid;
        if (i < N1 * K1) g_W1[i] = __float2half_rn(W1[i]);
        if (i < N2 * N1) g_W2[i] = __float2half_rn(W2[i]);
        return;
    }

    const int bq = job;
    const int b  = bq >> 7;

    const int* sp = spans + (size_t)bq * 4;
    const int as = sp[0], ae = sp[1], os = sp[2], oe = sp[3];
    const bool av = (as >= 2) && (ae >= as);
    const bool ov = (os >= 2) && (oe >= os);

    const float* base = hs + (size_t)b * LL * HH + 4 * tid;

    float4 aacc = {0.f, 0.f, 0.f, 0.f};
    float4 oacc = {0.f, 0.f, 0.f, 0.f};

    {
        const int s = av ? as : 1;
        const int e = av ? ae : 1;
        const float inv = 1.0f / (float)(e - s + 1);
        #pragma unroll
        for (int i = 0; i < 8; ++i) {
            const int r = s + i;
            if (r <= e) {
                const float4 v = *(const float4*)(base + (size_t)r * HH);
                aacc.x += v.x; aacc.y += v.y; aacc.z += v.z; aacc.w += v.w;
            }
        }
        aacc.x *= inv; aacc.y *= inv; aacc.z *= inv; aacc.w *= inv;
    }
    {
        const int s = ov ? os : 1;
        const int e = ov ? oe : 1;
        const float inv = 1.0f / (float)(e - s + 1);
        #pragma unroll
        for (int i = 0; i < 8; ++i) {
            const int r = s + i;
            if (r <= e) {
                const float4 v = *(const float4*)(base + (size_t)r * HH);
                oacc.x += v.x; oacc.y += v.y; oacc.z += v.z; oacc.w += v.w;
            }
        }
        oacc.x *= inv; oacc.y *= inv; oacc.z *= inv; oacc.w *= inv;
    }

    float4 pacc;
    pacc.x = aacc.x * oacc.x;  pacc.y = aacc.y * oacc.y;
    pacc.z = aacc.z * oacc.z;  pacc.w = aacc.w * oacc.w;

    const size_t rowoff = (size_t)bq * K1 + 4 * tid;
    store_h4(g_A, rowoff,          aacc);
    store_h4(g_A, rowoff + HH,     oacc);
    store_h4(g_A, rowoff + 2 * HH, pacc);
}

// ---------------------------------------------------------------------------
// GEMM tile body (R12's kernel as a device function).
// BM=32, BN=64*NTP, 8 warps (2M x 4N); 2 K-chunks (64 K) per pipeline stage;
// 2-stage cp.async double buffering; conflict-free 20-word-row smem layout.
// MODE 1: out_h = gelu(acc+bias) fp16
// MODE 3: fused head (requires BN == 128)
// ---------------------------------------------------------------------------
template<int NTP, int MODE>
__device__ void gemm_tile(int m0, int n0,
                          const __half* __restrict__ A,
                          const __half* __restrict__ B,
                          int lda, int ldb, int K,
                          const float* __restrict__ bias,
                          __half* __restrict__ out_h, int out_ld,
                          const float* __restrict__ W3,
                          const float* __restrict__ b3,
                          const float* __restrict__ mask,
                          float* __restrict__ out_final)
{
    constexpr int BM    = 32;
    constexpr int BN    = 64 * NTP;
    constexpr int AWd   = BM * 20;          // words per A chunk buffer
    constexpr int BWd   = BN * 20;          // words per B chunk buffer
    constexpr int CHWd  = AWd + BWd;        // words per chunk
    constexpr int STWd  = 2 * CHWd;         // words per stage (2 chunks)
    constexpr int TOT16 = (BM + BN) * 4;    // 16B units per chunk
    constexpr int UNITS = (TOT16 + 255) / 256;

    extern __shared__ uint32_t sm[];
    const uint32_t smem32 = smem_u32(sm);

    const int tid   = threadIdx.x;
    const int warp  = tid >> 5;
    const int lane  = tid & 31;
    const int warpM = warp >> 2;
    const int warpN = warp & 3;
    const int lane4 = lane >> 2;
    const int lanem = lane & 3;

    const int ns = K >> 6;                  // stages of 64 K

    const uint32_t aLaneOff = ((lane & 15) * 20 + ((lane >> 4) << 2)) * 4;
    const uint32_t bLaneOff = (((lane & 7) + ((lane >> 4) << 3)) * 20
                               + (((lane >> 3) & 1) << 2)) * 4;
    const uint32_t aWarpOff = (uint32_t)(warpM * 16) * 80;
    const uint32_t bWarpOff = (uint32_t)(warpN * (NTP * 16)) * 80;

    auto load_stage = [&](int s) {
        const uint32_t sb = smem32 + (uint32_t)(s & 1) * (STWd * 4);
        #pragma unroll
        for (int ch = 0; ch < 2; ++ch) {
            const int kk = (2 * s + ch) * 32;
            const uint32_t cb = sb + (uint32_t)ch * (CHWd * 4);
            #pragma unroll
            for (int i = 0; i < UNITS; ++i) {
                const int u = i * 256 + tid;
                if (UNITS * 256 != TOT16 && u >= TOT16) break;
                const __half* src;
                uint32_t dstw;
                if (u < BM * 4) {
                    const int row = u >> 2, seg = u & 3;
                    src  = A + (size_t)(m0 + row) * lda + kk + seg * 8;
                    dstw = row * 20 + seg * 4;
                } else {
                    const int v = u - BM * 4;
                    const int row = v >> 2, seg = v & 3;
                    src  = B + (size_t)(n0 + row) * ldb + kk + seg * 8;
                    dstw = AWd + row * 20 + seg * 4;
                }
                CP_ASYNC16(cb + dstw * 4, src);
            }
        }
        CP_COMMIT();
    };

    float acc[2 * NTP][4];
    #pragma unroll
    for (int j = 0; j < 2 * NTP; ++j)
        #pragma unroll
        for (int k = 0; k < 4; ++k) acc[j][k] = 0.f;

    load_stage(0);

    for (int s = 0; s < ns; ++s) {
        if (s + 1 < ns) { load_stage(s + 1); CP_WAIT1(); }
        else            { CP_WAIT0(); }
        __syncthreads();

        const uint32_t sb = smem32 + (uint32_t)(s & 1) * (STWd * 4);

        #pragma unroll
        for (int ch = 0; ch < 2; ++ch) {
            const uint32_t cb = sb + (uint32_t)ch * (CHWd * 4);
            const uint32_t aB = cb + aWarpOff + aLaneOff;
            const uint32_t bB = cb + AWd * 4 + bWarpOff + bLaneOff;

            #pragma unroll
            for (int sub = 0; sub < 2; ++sub) {
                uint32_t af[4];
                ldsm4(af, aB + sub * 32);

                #pragma unroll
                for (int ntp = 0; ntp < NTP; ++ntp) {
                    uint32_t bf[4];
                    ldsm4(bf, bB + (uint32_t)ntp * (16 * 80) + sub * 32);
                    #pragma unroll
                    for (int hf = 0; hf < 2; ++hf)
                        mma16816(acc[ntp * 2 + hf], af, bf + hf * 2);
                }
            }
        }
        __syncthreads();
    }

    // ---- epilogue ----
    if (MODE == 1) {
        #pragma unroll
        for (int nt = 0; nt < 2 * NTP; ++nt) {
            const int c0 = n0 + warpN * (NTP * 16) + nt * 8 + lanem * 2;
            const int r0 = m0 + warpM * 16 + lane4;
            const float bv0 = bias[c0];
            const float bv1 = bias[c0 + 1];
            *(__half2*)(out_h + (size_t)r0 * out_ld + c0) =
                __halves2half2(__float2half_rn(gelu_exact(acc[nt][0] + bv0)),
                               __float2half_rn(gelu_exact(acc[nt][1] + bv1)));
            *(__half2*)(out_h + (size_t)(r0 + 8) * out_ld + c0) =
                __halves2half2(__float2half_rn(gelu_exact(acc[nt][2] + bv0)),
                               __float2half_rn(gelu_exact(acc[nt][3] + bv1)));
        }
    } else {
        // MODE 3: stage gelu'd x2 tile (32 x 128 fp32, pad 132) into smem
        float* xs = (float*)sm;
        __syncthreads();   // mainloop smem reads done before overwrite
        #pragma unroll
        for (int nt = 0; nt < 2 * NTP; ++nt) {
            const int cl = warpN * (NTP * 16) + nt * 8 + lanem * 2;  // 0..127
            const int rl = warpM * 16 + lane4;                        // 0..15
            const float bv0 = bias[n0 + cl];
            const float bv1 = bias[n0 + cl + 1];
            xs[rl * 132 + cl]           = gelu_exact(acc[nt][0] + bv0);
            xs[rl * 132 + cl + 1]       = gelu_exact(acc[nt][1] + bv1);
            xs[(rl + 8) * 132 + cl]     = gelu_exact(acc[nt][2] + bv0);
            xs[(rl + 8) * 132 + cl + 1] = gelu_exact(acc[nt][3] + bv1);
        }
        __syncthreads();

        // head: warp w handles local rows 4w..4w+3
        const float4 w0 = ((const float4*)W3)[lane];        // row 0 of W3
        const float4 w1 = ((const float4*)W3)[32 + lane];   // row 1 of W3
        const float b30 = b3[0], b31 = b3[1];

        #pragma unroll
        for (int i = 0; i < 4; ++i) {
            const int lr  = warp * 4 + i;
            const int row = m0 + lr;
            const float4 xv = *(const float4*)(xs + lr * 132 + lane * 4);
            float s0 = xv.x * w0.x + xv.y * w0.y + xv.z * w0.z + xv.w * w0.w;
            float s1 = xv.x * w1.x + xv.y * w1.y + xv.z * w1.z + xv.w * w1.w;
            #pragma unroll
            for (int off = 16; off > 0; off >>= 1) {
                s0 += __shfl_xor_sync(0xFFFFFFFFu, s0, off);
                s1 += __shfl_xor_sync(0xFFFFFFFFu, s1, off);
            }
            if (lane == 0) {
                const float mk = (mask[row] >= 0.5f) ? 1.0f : 0.0f;
                const float v0 = (1.0f / (1.0f + expf(-(s0 + b30)))) * 8.0f + 1.0f;
                const float v1 = (1.0f / (1.0f + expf(-(s1 + b31)))) * 8.0f + 1.0f;
                out_final[row * 2 + 0] = v0 * mk;
                out_final[row * 2 + 1] = v1 * mk;
            }
        }
        __syncthreads();   // xs reuse safety if this block runs another tile
    }
}

// 2 stages x 2 chunks x (32+128)*20 words * 4 B = 51200 B
#define GEMM_SMEM (2 * 2 * (32 * 20 + 128 * 20) * 4)

// ---------------------------------------------------------------------------
// Persistent mega-kernel: pool+prep -> barrier -> GEMM1 -> barrier -> GEMM2+head
// 256 CTAs, __launch_bounds__(256, 2) guarantees co-residency (2/SM x 148 = 296).
// ---------------------------------------------------------------------------
__global__ __launch_bounds__(256, 2)
void mega_kernel(const float* __restrict__ hidden,
                 const int* __restrict__ spans,
                 const float* __restrict__ mask,
                 const float* __restrict__ W1,
                 const float* __restrict__ b1,
                 const float* __restrict__ W2,
                 const float* __restrict__ b2,
                 const float* __restrict__ W3,
                 const float* __restrict__ b3,
                 float* __restrict__ out)
{
    // phase 1: pooling + weight prep (grid-stride over 7168 jobs)
    for (int job = blockIdx.x; job < POOL_JOBS; job += gridDim.x)
        pool_prep_job(job, hidden, spans, W1, W2);

    grid_barrier();

    // phase 2: layer 1 — 256 tiles (1:1 with CTAs): m-tile = t>>1, n-half = t&1
    for (int t = blockIdx.x; t < (BQ / 32) * (N1 / 128); t += gridDim.x)
        gemm_tile<2, 1>((t >> 1) * 32, (t & 1) * 128,
                        g_A, g_W1, K1, K1, K1, b1, g_x1, N1,
                        nullptr, nullptr, nullptr, nullptr);

    grid_barrier();

    // phase 3: layer 2 + head — 128 tiles
    for (int t = blockIdx.x; t < BQ / 32; t += gridDim.x)
        gemm_tile<2, 3>(t * 32, 0,
                        g_x1, g_W2, N1, N1, N1, b2, nullptr, 0,
                        W3, b3, mask, out);
}

// ---------------------------------------------------------------------------
// Launch
// ---------------------------------------------------------------------------
extern "C" void kernel_launch(void* const* d_in, const int* in_sizes, int n_in,
                              void* d_out, int out_size)
{
    const float* hidden = (const float*)d_in[0];
    const int*   spans  = (const int*)d_in[1];
    const float* mask   = (const float*)d_in[2];
    const float* W1     = (const float*)d_in[3];
    const float* b1     = (const float*)d_in[4];
    const float* W2     = (const float*)d_in[5];
    const float* b2     = (const float*)d_in[6];
    const float* W3     = (const float*)d_in[7];
    const float* b3     = (const float*)d_in[8];
    float*       out    = (float*)d_out;

    cudaFuncSetAttribute((const void*)mega_kernel,
                         cudaFuncAttributeMaxDynamicSharedMemorySize, GEMM_SMEM);

    mega_kernel<<<GRID_CTAS, 256, GEMM_SMEM>>>(
        hidden, spans, mask, W1, b1, W2, b2, W3, b3, out);
}

// round 15
// speedup vs baseline: 1.1830x; 1.1830x over previous
#include <cuda_runtime.h>
#include <cuda_fp16.h>
#include <math.h>
#include <stdint.h>

// Problem constants
#define BB   32
#define LL   512
#define HH   1024
#define QQ   128
#define BQ   (BB * QQ)        // 4096 pair rows
#define K1   (3 * HH)          // 3072
#define N1   256               // VA_H
#define N2   128               // VA_H/2

// Scratch (static device globals)
__device__ __half g_A[(size_t)BQ * K1];     // pooled pair features, fp16
__device__ __half g_W1[(size_t)N1 * K1];    // fp16 weights
__device__ __half g_W2[(size_t)N2 * N1];
__device__ __half g_x1[(size_t)BQ * N1];    // gelu(layer1), fp16

// ---------------------------------------------------------------------------
// helpers
// ---------------------------------------------------------------------------
__device__ __forceinline__ uint32_t smem_u32(const void* p) {
    uint32_t a;
    asm("{ .reg .u64 t; cvta.to.shared.u64 t, %1; cvt.u32.u64 %0, t; }"
        : "=r"(a) : "l"(p));
    return a;
}

#define CP_ASYNC16(dst, src) \
    asm volatile("cp.async.cg.shared.global [%0], [%1], 16;" :: "r"(dst), "l"(src) : "memory")
#define CP_COMMIT() asm volatile("cp.async.commit_group;" ::: "memory")
#define CP_WAIT0()  asm volatile("cp.async.wait_group 0;" ::: "memory")
#define CP_WAIT1()  asm volatile("cp.async.wait_group 1;" ::: "memory")

__device__ __forceinline__ void mma16816(float c[4],
                                         const uint32_t a[4],
                                         const uint32_t b[2])
{
    asm volatile(
        "mma.sync.aligned.m16n8k16.row.col.f32.f16.f16.f32 "
        "{%0,%1,%2,%3}, {%4,%5,%6,%7}, {%8,%9}, {%0,%1,%2,%3};\n"
        : "+f"(c[0]), "+f"(c[1]), "+f"(c[2]), "+f"(c[3])
        : "r"(a[0]), "r"(a[1]), "r"(a[2]), "r"(a[3]),
          "r"(b[0]), "r"(b[1]));
}

__device__ __forceinline__ void ldsm4(uint32_t r[4], uint32_t addr)
{
    asm volatile("ldmatrix.sync.aligned.m8n8.x4.shared.b16 {%0,%1,%2,%3}, [%4];"
        : "=r"(r[0]), "=r"(r[1]), "=r"(r[2]), "=r"(r[3]) : "r"(addr));
}

__device__ __forceinline__ float gelu_exact(float x) {
    return 0.5f * x * (1.0f + erff(x * 0.70710678118654752f));
}

__device__ __forceinline__ void store_h4(__half* dst, size_t idx, float4 v)
{
    __half2 hh[2] = {
        __halves2half2(__float2half_rn(v.x), __float2half_rn(v.y)),
        __halves2half2(__float2half_rn(v.z), __float2half_rn(v.w)) };
    *(uint2*)(dst + idx) = *(uint2*)hh;
}

// ---------------------------------------------------------------------------
// Fused pooling + weight-prep kernel (R12 shape: regs-light, occ ~65%).
// ---------------------------------------------------------------------------
__global__ void pool_prep_kernel(const float* __restrict__ hs,
                                 const int* __restrict__ spans,
                                 const float* __restrict__ W1,
                                 const float* __restrict__ W2)
{
    if (blockIdx.x >= BQ) {
        const int i = (blockIdx.x - BQ) * 256 + threadIdx.x;
        if (i < N1 * K1) g_W1[i] = __float2half_rn(W1[i]);
        if (i < N2 * N1) g_W2[i] = __float2half_rn(W2[i]);
        return;
    }

    const int bq  = blockIdx.x;
    const int b   = bq >> 7;
    const int tid = threadIdx.x;

    const int* sp = spans + (size_t)bq * 4;
    const int as = sp[0], ae = sp[1], os = sp[2], oe = sp[3];
    const bool av = (as >= 2) && (ae >= as);
    const bool ov = (os >= 2) && (oe >= os);

    const float* base = hs + (size_t)b * LL * HH + 4 * tid;

    float4 aacc = {0.f, 0.f, 0.f, 0.f};
    float4 oacc = {0.f, 0.f, 0.f, 0.f};

    {
        const int s = av ? as : 1;
        const int e = av ? ae : 1;
        const float inv = 1.0f / (float)(e - s + 1);
        #pragma unroll
        for (int i = 0; i < 8; ++i) {
            const int r = s + i;
            if (r <= e) {
                const float4 v = *(const float4*)(base + (size_t)r * HH);
                aacc.x += v.x; aacc.y += v.y; aacc.z += v.z; aacc.w += v.w;
            }
        }
        aacc.x *= inv; aacc.y *= inv; aacc.z *= inv; aacc.w *= inv;
    }
    {
        const int s = ov ? os : 1;
        const int e = ov ? oe : 1;
        const float inv = 1.0f / (float)(e - s + 1);
        #pragma unroll
        for (int i = 0; i < 8; ++i) {
            const int r = s + i;
            if (r <= e) {
                const float4 v = *(const float4*)(base + (size_t)r * HH);
                oacc.x += v.x; oacc.y += v.y; oacc.z += v.z; oacc.w += v.w;
            }
        }
        oacc.x *= inv; oacc.y *= inv; oacc.z *= inv; oacc.w *= inv;
    }

    float4 pacc;
    pacc.x = aacc.x * oacc.x;  pacc.y = aacc.y * oacc.y;
    pacc.z = aacc.z * oacc.z;  pacc.w = aacc.w * oacc.w;

    const size_t rowoff = (size_t)bq * K1 + 4 * tid;
    store_h4(g_A, rowoff,          aacc);
    store_h4(g_A, rowoff + HH,     oacc);
    store_h4(g_A, rowoff + 2 * HH, pacc);
}

// ---------------------------------------------------------------------------
// Pipelined pure-fp16 mma.sync GEMM (R12 body), fp32 accum, ldmatrix.
// BM=32, BN=64*NTP, 8 warps (2M x 4N); 2 K-chunks (64 K) per stage;
// 2-stage cp.async double buffering; conflict-free 20-word-row smem layout.
// Entry: cudaGridDependencySynchronize() — PDL-safe wait on producer kernel.
// mode 1: out_h = gelu(acc+bias)  fp16
// mode 3: fused head (requires BN == 128)
// ---------------------------------------------------------------------------
template<int NTP, int MODE>
__global__ __launch_bounds__(256)
void mma_gemm_kernel(const __half* __restrict__ A,
                     const __half* __restrict__ B,
                     int lda, int ldb, int K,
                     const float* __restrict__ bias,
                     __half* __restrict__ out_h, int out_ld,
                     const float* __restrict__ W3,
                     const float* __restrict__ b3,
                     const float* __restrict__ mask,
                     float* __restrict__ out_final)
{
#if __CUDA_ARCH__ >= 900
    cudaGridDependencySynchronize();
#endif

    constexpr int BM    = 32;
    constexpr int BN    = 64 * NTP;
    constexpr int AWd   = BM * 20;          // words per A chunk buffer
    constexpr int BWd   = BN * 20;          // words per B chunk buffer
    constexpr int CHWd  = AWd + BWd;        // words per chunk
    constexpr int STWd  = 2 * CHWd;         // words per stage (2 chunks)
    constexpr int TOT16 = (BM + BN) * 4;    // 16B units per chunk
    constexpr int UNITS = (TOT16 + 255) / 256;

    extern __shared__ uint32_t sm[];
    const uint32_t smem32 = smem_u32(sm);

    const int tid   = threadIdx.x;
    const int warp  = tid >> 5;
    const int lane  = tid & 31;
    const int warpM = warp >> 2;
    const int warpN = warp & 3;
    const int lane4 = lane >> 2;
    const int lanem = lane & 3;

    const int m0 = blockIdx.y * BM;
    const int n0 = blockIdx.x * BN;
    const int ns = K >> 6;                  // stages of 64 K

    const uint32_t aLaneOff = ((lane & 15) * 20 + ((lane >> 4) << 2)) * 4;
    const uint32_t bLaneOff = (((lane & 7) + ((lane >> 4) << 3)) * 20
                               + (((lane >> 3) & 1) << 2)) * 4;
    const uint32_t aWarpOff = (uint32_t)(warpM * 16) * 80;
    const uint32_t bWarpOff = (uint32_t)(warpN * (NTP * 16)) * 80;

    auto load_stage = [&](int s) {
        const uint32_t sb = smem32 + (uint32_t)(s & 1) * (STWd * 4);
        #pragma unroll
        for (int ch = 0; ch < 2; ++ch) {
            const int kk = (2 * s + ch) * 32;
            const uint32_t cb = sb + (uint32_t)ch * (CHWd * 4);
            #pragma unroll
            for (int i = 0; i < UNITS; ++i) {
                const int u = i * 256 + tid;
                if (UNITS * 256 != TOT16 && u >= TOT16) break;
                const __half* src;
                uint32_t dstw;
                if (u < BM * 4) {
                    const int row = u >> 2, seg = u & 3;
                    src  = A + (size_t)(m0 + row) * lda + kk + seg * 8;
                    dstw = row * 20 + seg * 4;
                } else {
                    const int v = u - BM * 4;
                    const int row = v >> 2, seg = v & 3;
                    src  = B + (size_t)(n0 + row) * ldb + kk + seg * 8;
                    dstw = AWd + row * 20 + seg * 4;
                }
                CP_ASYNC16(cb + dstw * 4, src);
            }
        }
        CP_COMMIT();
    };

    float acc[2 * NTP][4];
    #pragma unroll
    for (int j = 0; j < 2 * NTP; ++j)
        #pragma unroll
        for (int k = 0; k < 4; ++k) acc[j][k] = 0.f;

    load_stage(0);

    for (int s = 0; s < ns; ++s) {
        if (s + 1 < ns) { load_stage(s + 1); CP_WAIT1(); }
        else            { CP_WAIT0(); }
        __syncthreads();

        const uint32_t sb = smem32 + (uint32_t)(s & 1) * (STWd * 4);

        #pragma unroll
        for (int ch = 0; ch < 2; ++ch) {
            const uint32_t cb = sb + (uint32_t)ch * (CHWd * 4);
            const uint32_t aB = cb + aWarpOff + aLaneOff;
            const uint32_t bB = cb + AWd * 4 + bWarpOff + bLaneOff;

            #pragma unroll
            for (int sub = 0; sub < 2; ++sub) {
                uint32_t af[4];
                ldsm4(af, aB + sub * 32);

                #pragma unroll
                for (int ntp = 0; ntp < NTP; ++ntp) {
                    uint32_t bf[4];
                    ldsm4(bf, bB + (uint32_t)ntp * (16 * 80) + sub * 32);
                    #pragma unroll
                    for (int hf = 0; hf < 2; ++hf)
                        mma16816(acc[ntp * 2 + hf], af, bf + hf * 2);
                }
            }
        }
        __syncthreads();
    }

    // ---- epilogue ----
    if (MODE == 1) {
        #pragma unroll
        for (int nt = 0; nt < 2 * NTP; ++nt) {
            const int c0 = n0 + warpN * (NTP * 16) + nt * 8 + lanem * 2;
            const int r0 = m0 + warpM * 16 + lane4;
            const float bv0 = bias[c0];
            const float bv1 = bias[c0 + 1];
            *(__half2*)(out_h + (size_t)r0 * out_ld + c0) =
                __halves2half2(__float2half_rn(gelu_exact(acc[nt][0] + bv0)),
                               __float2half_rn(gelu_exact(acc[nt][1] + bv1)));
            *(__half2*)(out_h + (size_t)(r0 + 8) * out_ld + c0) =
                __halves2half2(__float2half_rn(gelu_exact(acc[nt][2] + bv0)),
                               __float2half_rn(gelu_exact(acc[nt][3] + bv1)));
        }
    } else {
        // MODE 3: stage gelu'd x2 tile (32 x 128 fp32, pad 132) into smem
        float* xs = (float*)sm;
        __syncthreads();   // mainloop smem reads done before overwrite
        #pragma unroll
        for (int nt = 0; nt < 2 * NTP; ++nt) {
            const int cl = warpN * (NTP * 16) + nt * 8 + lanem * 2;  // 0..127
            const int rl = warpM * 16 + lane4;                        // 0..15
            const float bv0 = bias[n0 + cl];
            const float bv1 = bias[n0 + cl + 1];
            xs[rl * 132 + cl]           = gelu_exact(acc[nt][0] + bv0);
            xs[rl * 132 + cl + 1]       = gelu_exact(acc[nt][1] + bv1);
            xs[(rl + 8) * 132 + cl]     = gelu_exact(acc[nt][2] + bv0);
            xs[(rl + 8) * 132 + cl + 1] = gelu_exact(acc[nt][3] + bv1);
        }
        __syncthreads();

        // head: warp w handles local rows 4w..4w+3
        const float4 w0 = ((const float4*)W3)[lane];        // row 0 of W3
        const float4 w1 = ((const float4*)W3)[32 + lane];   // row 1 of W3
        const float b30 = b3[0], b31 = b3[1];

        #pragma unroll
        for (int i = 0; i < 4; ++i) {
            const int lr  = warp * 4 + i;
            const int row = m0 + lr;
            const float4 xv = *(const float4*)(xs + lr * 132 + lane * 4);
            float s0 = xv.x * w0.x + xv.y * w0.y + xv.z * w0.z + xv.w * w0.w;
            float s1 = xv.x * w1.x + xv.y * w1.y + xv.z * w1.z + xv.w * w1.w;
            #pragma unroll
            for (int off = 16; off > 0; off >>= 1) {
                s0 += __shfl_xor_sync(0xFFFFFFFFu, s0, off);
                s1 += __shfl_xor_sync(0xFFFFFFFFu, s1, off);
            }
            if (lane == 0) {
                const float mk = (mask[row] >= 0.5f) ? 1.0f : 0.0f;
                const float v0 = (1.0f / (1.0f + expf(-(s0 + b30)))) * 8.0f + 1.0f;
                const float v1 = (1.0f / (1.0f + expf(-(s1 + b31)))) * 8.0f + 1.0f;
                out_final[row * 2 + 0] = v0 * mk;
                out_final[row * 2 + 1] = v1 * mk;
            }
        }
    }
}

// 2 stages x 2 chunks x (32+128)*20 words * 4 B = 51200 B
#define GEMM_SMEM (2 * 2 * (32 * 20 + 128 * 20) * 4)

// ---------------------------------------------------------------------------
// Launch — GEMMs use Programmatic Dependent Launch to hide launch/tail gaps.
// ---------------------------------------------------------------------------
extern "C" void kernel_launch(void* const* d_in, const int* in_sizes, int n_in,
                              void* d_out, int out_size)
{
    const float* hidden = (const float*)d_in[0];
    const int*   spans  = (const int*)d_in[1];
    const float* mask   = (const float*)d_in[2];
    const float* W1     = (const float*)d_in[3];
    const float* b1     = (const float*)d_in[4];
    const float* W2     = (const float*)d_in[5];
    const float* b2     = (const float*)d_in[6];
    const float* W3     = (const float*)d_in[7];
    const float* b3     = (const float*)d_in[8];
    float*       out    = (float*)d_out;

    __half *A, *W1h, *W2h, *x1;
    cudaGetSymbolAddress((void**)&A,   g_A);
    cudaGetSymbolAddress((void**)&W1h, g_W1);
    cudaGetSymbolAddress((void**)&W2h, g_W2);
    cudaGetSymbolAddress((void**)&x1,  g_x1);

    cudaFuncSetAttribute((const void*)mma_gemm_kernel<2, 1>,
                         cudaFuncAttributeMaxDynamicSharedMemorySize, GEMM_SMEM);
    cudaFuncSetAttribute((const void*)mma_gemm_kernel<2, 3>,
                         cudaFuncAttributeMaxDynamicSharedMemorySize, GEMM_SMEM);

    // 1) fused pooling (blocks 0..4095) + weight prep (blocks 4096..7167)
    pool_prep_kernel<<<BQ + (N1 * K1 + 255) / 256, 256>>>(hidden, spans, W1, W2);

    cudaLaunchAttribute pdl[1];
    pdl[0].id = cudaLaunchAttributeProgrammaticStreamSerialization;
    pdl[0].val.programmaticStreamSerializationAllowed = 1;

    // 2) layer 1: grid (2, 128) = 256 CTAs, fused bias+gelu -> fp16 x1 (PDL)
    {
        cudaLaunchConfig_t cfg = {};
        cfg.gridDim  = dim3(N1 / 128, BQ / 32, 1);
        cfg.blockDim = dim3(256, 1, 1);
        cfg.dynamicSmemBytes = GEMM_SMEM;
        cfg.stream = 0;
        cfg.attrs = pdl;
        cfg.numAttrs = 1;
        cudaLaunchKernelEx(&cfg, mma_gemm_kernel<2, 1>,
                           (const __half*)A, (const __half*)W1h,
                           (int)K1, (int)K1, (int)K1, b1, x1, (int)N1,
                           (const float*)nullptr, (const float*)nullptr,
                           (const float*)nullptr, (float*)nullptr);
    }

    // 3) layer 2 + head fused: grid (1, 128) = 128 CTAs (PDL)
    {
        cudaLaunchConfig_t cfg = {};
        cfg.gridDim  = dim3(N2 / 128, BQ / 32, 1);
        cfg.blockDim = dim3(256, 1, 1);
        cfg.dynamicSmemBytes = GEMM_SMEM;
        cfg.stream = 0;
        cfg.attrs = pdl;
        cfg.numAttrs = 1;
        cudaLaunchKernelEx(&cfg, mma_gemm_kernel<2, 3>,
                           (const __half*)x1, (const __half*)W2h,
                           (int)N1, (int)N1, (int)N1, b2,
                           (__half*)nullptr, 0,
                           W3, b3, mask, out);
    }
}

// round 16
// speedup vs baseline: 1.2559x; 1.0616x over previous
#include <cuda_runtime.h>
#include <cuda_fp16.h>
#include <math.h>
#include <stdint.h>

// Problem constants
#define BB   32
#define LL   512
#define HH   1024
#define QQ   128
#define BQ   (BB * QQ)        // 4096 pair rows
#define K1   (3 * HH)          // 3072
#define N1   256               // VA_H
#define N2   128               // VA_H/2

// Scratch (static device globals)
__device__ __half g_A[(size_t)BQ * K1];     // pooled pair features, fp16
__device__ __half g_W1[(size_t)N1 * K1];    // fp16 weights
__device__ __half g_W2[(size_t)N2 * N1];
__device__ __half g_x1[(size_t)BQ * N1];    // gelu(layer1), fp16
__device__ int    g_done[BQ / 32];          // per-mtile arrival counters (self-reset)

// ---------------------------------------------------------------------------
// helpers
// ---------------------------------------------------------------------------
__device__ __forceinline__ uint32_t smem_u32(const void* p) {
    uint32_t a;
    asm("{ .reg .u64 t; cvta.to.shared.u64 t, %1; cvt.u32.u64 %0, t; }"
        : "=r"(a) : "l"(p));
    return a;
}

#define CP_ASYNC16(dst, src) \
    asm volatile("cp.async.cg.shared.global [%0], [%1], 16;" :: "r"(dst), "l"(src) : "memory")
#define CP_COMMIT() asm volatile("cp.async.commit_group;" ::: "memory")
#define CP_WAIT0()  asm volatile("cp.async.wait_group 0;" ::: "memory")
#define CP_WAIT1()  asm volatile("cp.async.wait_group 1;" ::: "memory")

__device__ __forceinline__ void mma16816(float c[4],
                                         const uint32_t a[4],
                                         const uint32_t b[2])
{
    asm volatile(
        "mma.sync.aligned.m16n8k16.row.col.f32.f16.f16.f32 "
        "{%0,%1,%2,%3}, {%4,%5,%6,%7}, {%8,%9}, {%0,%1,%2,%3};\n"
        : "+f"(c[0]), "+f"(c[1]), "+f"(c[2]), "+f"(c[3])
        : "r"(a[0]), "r"(a[1]), "r"(a[2]), "r"(a[3]),
          "r"(b[0]), "r"(b[1]));
}

__device__ __forceinline__ void ldsm4(uint32_t r[4], uint32_t addr)
{
    asm volatile("ldmatrix.sync.aligned.m8n8.x4.shared.b16 {%0,%1,%2,%3}, [%4];"
        : "=r"(r[0]), "=r"(r[1]), "=r"(r[2]), "=r"(r[3]) : "r"(addr));
}

__device__ __forceinline__ float gelu_exact(float x) {
    return 0.5f * x * (1.0f + erff(x * 0.70710678118654752f));
}

__device__ __forceinline__ void store_h4(__half* dst, size_t idx, float4 v)
{
    __half2 hh[2] = {
        __halves2half2(__float2half_rn(v.x), __float2half_rn(v.y)),
        __halves2half2(__float2half_rn(v.z), __float2half_rn(v.w)) };
    *(uint2*)(dst + idx) = *(uint2*)hh;
}

// ---------------------------------------------------------------------------
// Fused pooling + weight-prep kernel (R12/R15 shape: regs-light, occ ~65%).
// ---------------------------------------------------------------------------
__global__ void pool_prep_kernel(const float* __restrict__ hs,
                                 const int* __restrict__ spans,
                                 const float* __restrict__ W1,
                                 const float* __restrict__ W2)
{
    if (blockIdx.x >= BQ) {
        const int i = (blockIdx.x - BQ) * 256 + threadIdx.x;
        if (i < N1 * K1) g_W1[i] = __float2half_rn(W1[i]);
        if (i < N2 * N1) g_W2[i] = __float2half_rn(W2[i]);
        return;
    }

    const int bq  = blockIdx.x;
    const int b   = bq >> 7;
    const int tid = threadIdx.x;

    const int* sp = spans + (size_t)bq * 4;
    const int as = sp[0], ae = sp[1], os = sp[2], oe = sp[3];
    const bool av = (as >= 2) && (ae >= as);
    const bool ov = (os >= 2) && (oe >= os);

    const float* base = hs + (size_t)b * LL * HH + 4 * tid;

    float4 aacc = {0.f, 0.f, 0.f, 0.f};
    float4 oacc = {0.f, 0.f, 0.f, 0.f};

    {
        const int s = av ? as : 1;
        const int e = av ? ae : 1;
        const float inv = 1.0f / (float)(e - s + 1);
        #pragma unroll
        for (int i = 0; i < 8; ++i) {
            const int r = s + i;
            if (r <= e) {
                const float4 v = *(const float4*)(base + (size_t)r * HH);
                aacc.x += v.x; aacc.y += v.y; aacc.z += v.z; aacc.w += v.w;
            }
        }
        aacc.x *= inv; aacc.y *= inv; aacc.z *= inv; aacc.w *= inv;
    }
    {
        const int s = ov ? os : 1;
        const int e = ov ? oe : 1;
        const float inv = 1.0f / (float)(e - s + 1);
        #pragma unroll
        for (int i = 0; i < 8; ++i) {
            const int r = s + i;
            if (r <= e) {
                const float4 v = *(const float4*)(base + (size_t)r * HH);
                oacc.x += v.x; oacc.y += v.y; oacc.z += v.z; oacc.w += v.w;
            }
        }
        oacc.x *= inv; oacc.y *= inv; oacc.z *= inv; oacc.w *= inv;
    }

    float4 pacc;
    pacc.x = aacc.x * oacc.x;  pacc.y = aacc.y * oacc.y;
    pacc.z = aacc.z * oacc.z;  pacc.w = aacc.w * oacc.w;

    const size_t rowoff = (size_t)bq * K1 + 4 * tid;
    store_h4(g_A, rowoff,          aacc);
    store_h4(g_A, rowoff + HH,     oacc);
    store_h4(g_A, rowoff + 2 * HH, pacc);
}

// ---------------------------------------------------------------------------
// GEMM tile body (proven R12/R14 body). BM=32, BN=64*NTP, 8 warps (2M x 4N);
// 2 K-chunks (64 K) per pipeline stage; 2-stage cp.async double buffering;
// conflict-free 20-word-row smem layout.
// MODE 1: out_h = gelu(acc+bias) fp16
// MODE 3: fused head (requires BN == 128)
// ---------------------------------------------------------------------------
template<int NTP, int MODE>
__device__ void gemm_tile(int m0, int n0,
                          const __half* __restrict__ A,
                          const __half* __restrict__ B,
                          int lda, int ldb, int K,
                          const float* __restrict__ bias,
                          __half* __restrict__ out_h, int out_ld,
                          const float* __restrict__ W3,
                          const float* __restrict__ b3,
                          const float* __restrict__ mask,
                          float* __restrict__ out_final)
{
    constexpr int BM    = 32;
    constexpr int BN    = 64 * NTP;
    constexpr int AWd   = BM * 20;          // words per A chunk buffer
    constexpr int BWd   = BN * 20;          // words per B chunk buffer
    constexpr int CHWd  = AWd + BWd;        // words per chunk
    constexpr int STWd  = 2 * CHWd;         // words per stage (2 chunks)
    constexpr int TOT16 = (BM + BN) * 4;    // 16B units per chunk
    constexpr int UNITS = (TOT16 + 255) / 256;

    extern __shared__ uint32_t sm[];
    const uint32_t smem32 = smem_u32(sm);

    const int tid   = threadIdx.x;
    const int warp  = tid >> 5;
    const int lane  = tid & 31;
    const int warpM = warp >> 2;
    const int warpN = warp & 3;
    const int lane4 = lane >> 2;
    const int lanem = lane & 3;

    const int ns = K >> 6;                  // stages of 64 K

    const uint32_t aLaneOff = ((lane & 15) * 20 + ((lane >> 4) << 2)) * 4;
    const uint32_t bLaneOff = (((lane & 7) + ((lane >> 4) << 3)) * 20
                               + (((lane >> 3) & 1) << 2)) * 4;
    const uint32_t aWarpOff = (uint32_t)(warpM * 16) * 80;
    const uint32_t bWarpOff = (uint32_t)(warpN * (NTP * 16)) * 80;

    auto load_stage = [&](int s) {
        const uint32_t sb = smem32 + (uint32_t)(s & 1) * (STWd * 4);
        #pragma unroll
        for (int ch = 0; ch < 2; ++ch) {
            const int kk = (2 * s + ch) * 32;
            const uint32_t cb = sb + (uint32_t)ch * (CHWd * 4);
            #pragma unroll
            for (int i = 0; i < UNITS; ++i) {
                const int u = i * 256 + tid;
                if (UNITS * 256 != TOT16 && u >= TOT16) break;
                const __half* src;
                uint32_t dstw;
                if (u < BM * 4) {
                    const int row = u >> 2, seg = u & 3;
                    src  = A + (size_t)(m0 + row) * lda + kk + seg * 8;
                    dstw = row * 20 + seg * 4;
                } else {
                    const int v = u - BM * 4;
                    const int row = v >> 2, seg = v & 3;
                    src  = B + (size_t)(n0 + row) * ldb + kk + seg * 8;
                    dstw = AWd + row * 20 + seg * 4;
                }
                CP_ASYNC16(cb + dstw * 4, src);
            }
        }
        CP_COMMIT();
    };

    float acc[2 * NTP][4];
    #pragma unroll
    for (int j = 0; j < 2 * NTP; ++j)
        #pragma unroll
        for (int k = 0; k < 4; ++k) acc[j][k] = 0.f;

    load_stage(0);

    for (int s = 0; s < ns; ++s) {
        if (s + 1 < ns) { load_stage(s + 1); CP_WAIT1(); }
        else            { CP_WAIT0(); }
        __syncthreads();

        const uint32_t sb = smem32 + (uint32_t)(s & 1) * (STWd * 4);

        #pragma unroll
        for (int ch = 0; ch < 2; ++ch) {
            const uint32_t cb = sb + (uint32_t)ch * (CHWd * 4);
            const uint32_t aB = cb + aWarpOff + aLaneOff;
            const uint32_t bB = cb + AWd * 4 + bWarpOff + bLaneOff;

            #pragma unroll
            for (int sub = 0; sub < 2; ++sub) {
                uint32_t af[4];
                ldsm4(af, aB + sub * 32);

                #pragma unroll
                for (int ntp = 0; ntp < NTP; ++ntp) {
                    uint32_t bf[4];
                    ldsm4(bf, bB + (uint32_t)ntp * (16 * 80) + sub * 32);
                    #pragma unroll
                    for (int hf = 0; hf < 2; ++hf)
                        mma16816(acc[ntp * 2 + hf], af, bf + hf * 2);
                }
            }
        }
        __syncthreads();
    }

    // ---- epilogue ----
    if (MODE == 1) {
        #pragma unroll
        for (int nt = 0; nt < 2 * NTP; ++nt) {
            const int c0 = n0 + warpN * (NTP * 16) + nt * 8 + lanem * 2;
            const int r0 = m0 + warpM * 16 + lane4;
            const float bv0 = bias[c0];
            const float bv1 = bias[c0 + 1];
            *(__half2*)(out_h + (size_t)r0 * out_ld + c0) =
                __halves2half2(__float2half_rn(gelu_exact(acc[nt][0] + bv0)),
                               __float2half_rn(gelu_exact(acc[nt][1] + bv1)));
            *(__half2*)(out_h + (size_t)(r0 + 8) * out_ld + c0) =
                __halves2half2(__float2half_rn(gelu_exact(acc[nt][2] + bv0)),
                               __float2half_rn(gelu_exact(acc[nt][3] + bv1)));
        }
    } else {
        // MODE 3: stage gelu'd x2 tile (32 x 128 fp32, pad 132) into smem
        float* xs = (float*)sm;
        __syncthreads();   // mainloop smem reads done before overwrite
        #pragma unroll
        for (int nt = 0; nt < 2 * NTP; ++nt) {
            const int cl = warpN * (NTP * 16) + nt * 8 + lanem * 2;  // 0..127
            const int rl = warpM * 16 + lane4;                        // 0..15
            const float bv0 = bias[n0 + cl];
            const float bv1 = bias[n0 + cl + 1];
            xs[rl * 132 + cl]           = gelu_exact(acc[nt][0] + bv0);
            xs[rl * 132 + cl + 1]       = gelu_exact(acc[nt][1] + bv1);
            xs[(rl + 8) * 132 + cl]     = gelu_exact(acc[nt][2] + bv0);
            xs[(rl + 8) * 132 + cl + 1] = gelu_exact(acc[nt][3] + bv1);
        }
        __syncthreads();

        // head: warp w handles local rows 4w..4w+3
        const float4 w0 = ((const float4*)W3)[lane];        // row 0 of W3
        const float4 w1 = ((const float4*)W3)[32 + lane];   // row 1 of W3
        const float b30 = b3[0], b31 = b3[1];

        #pragma unroll
        for (int i = 0; i < 4; ++i) {
            const int lr  = warp * 4 + i;
            const int row = m0 + lr;
            const float4 xv = *(const float4*)(xs + lr * 132 + lane * 4);
            float s0 = xv.x * w0.x + xv.y * w0.y + xv.z * w0.z + xv.w * w0.w;
            float s1 = xv.x * w1.x + xv.y * w1.y + xv.z * w1.z + xv.w * w1.w;
            #pragma unroll
            for (int off = 16; off > 0; off >>= 1) {
                s0 += __shfl_xor_sync(0xFFFFFFFFu, s0, off);
                s1 += __shfl_xor_sync(0xFFFFFFFFu, s1, off);
            }
            if (lane == 0) {
                const float mk = (mask[row] >= 0.5f) ? 1.0f : 0.0f;
                const float v0 = (1.0f / (1.0f + expf(-(s0 + b30)))) * 8.0f + 1.0f;
                const float v1 = (1.0f / (1.0f + expf(-(s1 + b31)))) * 8.0f + 1.0f;
                out_final[row * 2 + 0] = v0 * mk;
                out_final[row * 2 + 1] = v1 * mk;
            }
        }
        __syncthreads();
    }
}

// 2 stages x 2 chunks x (32+128)*20 words * 4 B = 51200 B
#define GEMM_SMEM (2 * 2 * (32 * 20 + 128 * 20) * 4)

// ---------------------------------------------------------------------------
// Fused GEMM1 -> (last CTA per m-tile) GEMM2 + head.
// grid (2, 128): 2 n-halves x 128 m-tiles. Both n-half CTAs write their x1
// half, then the LAST arriver for each m-tile runs layer 2 + head for those
// 32 rows. g_done self-resets -> replay-deterministic.
// ---------------------------------------------------------------------------
__global__ __launch_bounds__(256)
void gemm_fused_kernel(const float* __restrict__ b1,
                       const float* __restrict__ b2,
                       const float* __restrict__ W3,
                       const float* __restrict__ b3,
                       const float* __restrict__ mask,
                       float* __restrict__ out)
{
#if __CUDA_ARCH__ >= 900
    cudaGridDependencySynchronize();
#endif

    const int mt = blockIdx.y;
    const int m0 = mt * 32;
    const int n0 = blockIdx.x * 128;

    // layer 1: x1[m0:m0+32, n0:n0+128] = gelu(A @ W1^T + b1)
    gemm_tile<2, 1>(m0, n0, g_A, g_W1, K1, K1, K1, b1, g_x1, N1,
                    nullptr, nullptr, nullptr, nullptr);

    // handshake: last arriver per m-tile chains layer 2 + head
    __shared__ int s_last;
    __threadfence();                 // make this thread's x1 stores device-visible
    __syncthreads();
    if (threadIdx.x == 0) {
        const int old = atomicAdd(&g_done[mt], 1);
        s_last = (old == 1);
    }
    __syncthreads();

    if (s_last) {
        __threadfence();             // acquire: partner's x1 half now visible
        gemm_tile<2, 3>(m0, 0, g_x1, g_W2, N1, N1, N1, b2, nullptr, 0,
                        W3, b3, mask, out);
        if (threadIdx.x == 0) g_done[mt] = 0;   // reset for next replay
    }
}

// ---------------------------------------------------------------------------
// Launch — pool/prep, then the fused GEMM kernel via PDL.
// ---------------------------------------------------------------------------
extern "C" void kernel_launch(void* const* d_in, const int* in_sizes, int n_in,
                              void* d_out, int out_size)
{
    const float* hidden = (const float*)d_in[0];
    const int*   spans  = (const int*)d_in[1];
    const float* mask   = (const float*)d_in[2];
    const float* W1     = (const float*)d_in[3];
    const float* b1     = (const float*)d_in[4];
    const float* W2     = (const float*)d_in[5];
    const float* b2     = (const float*)d_in[6];
    const float* W3     = (const float*)d_in[7];
    const float* b3     = (const float*)d_in[8];
    float*       out    = (float*)d_out;

    cudaFuncSetAttribute((const void*)gemm_fused_kernel,
                         cudaFuncAttributeMaxDynamicSharedMemorySize, GEMM_SMEM);

    // 1) fused pooling (blocks 0..4095) + weight prep (blocks 4096..7167)
    pool_prep_kernel<<<BQ + (N1 * K1 + 255) / 256, 256>>>(hidden, spans, W1, W2);

    // 2) GEMM1 + chained GEMM2/head, PDL off the pool kernel
    cudaLaunchAttribute pdl[1];
    pdl[0].id = cudaLaunchAttributeProgrammaticStreamSerialization;
    pdl[0].val.programmaticStreamSerializationAllowed = 1;

    cudaLaunchConfig_t cfg = {};
    cfg.gridDim  = dim3(2, BQ / 32, 1);
    cfg.blockDim = dim3(256, 1, 1);
    cfg.dynamicSmemBytes = GEMM_SMEM;
    cfg.stream = 0;
    cfg.attrs = pdl;
    cfg.numAttrs = 1;
    cudaLaunchKernelEx(&cfg, gemm_fused_kernel, b1, b2, W3, b3, mask, out);
}